// round 13
// baseline (speedup 1.0000x reference)
#include <cuda_runtime.h>
#include <cuda_fp16.h>
#include <math.h>
#include <cstdint>

// ---------------------------------------------------------------------------
// Problem dims (fixed by the dataset)
// ---------------------------------------------------------------------------
#define BATCH 4
#define SEQ   4096
#define FF    768
#define NH    12
#define DH    64
#define MROWS (BATCH*SEQ)     // 16384
#define BH    (BATCH*NH)      // 48
#define NSPLIT 32
#define NPS (SEQ / NSPLIT)    // 128 sequence rows per split

// ---------------------------------------------------------------------------
// Static device scratch (no runtime allocation allowed)
// ---------------------------------------------------------------------------
__device__ __half  g_x [MROWS * FF];
__device__ __half  g_q [MROWS * FF];
__device__ __half  g_k [MROWS * FF];
__device__ __half  g_v [MROWS * FF];
__device__ __half  g_n [MROWS * FF];
__device__ __half  g_w [4][FF * FF];              // transposed weights fp16 [n][k]
__device__ float  g_kvp[NSPLIT * BH * DH * DH];
__device__ float  g_ksp[NSPLIT * BH * DH];
__device__ __half g_kvT[BH * DH * DH];
__device__ float  g_ks [BH * DH];

// ---------------------------------------------------------------------------
// PTX helpers
// ---------------------------------------------------------------------------
__device__ __forceinline__ uint32_t smem_u32(const void* p) {
    uint32_t a;
    asm("{ .reg .u64 t; cvta.to.shared.u64 t, %1; cvt.u32.u64 %0, t; }"
        : "=r"(a) : "l"(p));
    return a;
}

__device__ __forceinline__ void cp16(uint32_t dst, const void* src) {
    asm volatile("cp.async.cg.shared.global [%0], [%1], 16;" :: "r"(dst), "l"(src));
}
#define CP_COMMIT() asm volatile("cp.async.commit_group;" ::: "memory")
template <int N>
__device__ __forceinline__ void cp_wait() {
    asm volatile("cp.async.wait_group %0;" :: "n"(N) : "memory");
}

__device__ __forceinline__ void ldsm_x4(uint32_t* r, uint32_t addr) {
    asm volatile("ldmatrix.sync.aligned.m8n8.x4.shared.b16 {%0,%1,%2,%3}, [%4];"
                 : "=r"(r[0]), "=r"(r[1]), "=r"(r[2]), "=r"(r[3]) : "r"(addr));
}
__device__ __forceinline__ void ldsm_x4_t(uint32_t* r, uint32_t addr) {
    asm volatile("ldmatrix.sync.aligned.m8n8.x4.trans.shared.b16 {%0,%1,%2,%3}, [%4];"
                 : "=r"(r[0]), "=r"(r[1]), "=r"(r[2]), "=r"(r[3]) : "r"(addr));
}

__device__ __forceinline__ void mma16816(float* d, const uint32_t* a, const uint32_t* b) {
    asm volatile(
        "mma.sync.aligned.m16n8k16.row.col.f32.f16.f16.f32 "
        "{%0,%1,%2,%3}, {%4,%5,%6,%7}, {%8,%9}, {%0,%1,%2,%3};"
        : "+f"(d[0]), "+f"(d[1]), "+f"(d[2]), "+f"(d[3])
        : "r"(a[0]), "r"(a[1]), "r"(a[2]), "r"(a[3]), "r"(b[0]), "r"(b[1]));
}

__device__ __forceinline__ void store2(float* C, size_t idx, float a, float b) {
    *(float2*)(C + idx) = make_float2(a, b);
}
__device__ __forceinline__ void store2(__half* C, size_t idx, float a, float b) {
    *(__half2*)(C + idx) = __floats2half2_rn(a, b);
}

// ---------------------------------------------------------------------------
// gemm core: C tile = A[M,K] @ W[N,K]^T + bias, optional phi
// CTA 128x128, BK=64, 256 threads = 8 warps (2Mx4N), warp 64x32.
// 3-stage cp.async ring (96KB), prefetch distance 2, ONE barrier/iter.
// Straight-line fragment loop (validated best at R9/R12).
// ---------------------------------------------------------------------------
#define GBM 128
#define GBN 128
#define GBK 64
#define A_BYTES  (128 * 128)
#define B_OFF  A_BYTES
#define STAGE_BYTES (2 * A_BYTES)      // 32 KB
#define SMEM_DYN (3 * STAGE_BYTES)     // 96 KB
#define NIT (FF / GBK)                 // 12

template <typename OutT>
__device__ __forceinline__ void gemm_core(
        const __half* __restrict__ A, const __half* __restrict__ B,
        const float* __restrict__ bias, OutT* __restrict__ C,
        bool phi, int brow, int bcol, char* dsm)
{
    const uint32_t sb = smem_u32(dsm);
    const int tid  = threadIdx.x;
    const int warp = tid >> 5;
    const int lane = tid & 31;
    const int wm   = warp & 1;
    const int wn   = warp >> 1;

    float acc[4][4][4];
    #pragma unroll
    for (int i = 0; i < 4; i++)
        #pragma unroll
        for (int j = 0; j < 4; j++)
            #pragma unroll
            for (int q = 0; q < 4; q++) acc[i][j][q] = 0.0f;

    const int lr = tid >> 3, lc = tid & 7;
    uint32_t swo[4];
    const __half* gA[4];
    const __half* gB[4];
    #pragma unroll
    for (int i = 0; i < 4; i++) {
        const int row = lr + 32 * i;
        swo[i] = (uint32_t)row * 128 + (uint32_t)((lc ^ (row & 7)) << 4);
        gA[i] = A + (size_t)(brow + row) * FF + lc * 8;
        gB[i] = B + (size_t)(bcol + row) * FF + lc * 8;
    }

    const uint32_t stb[3] = { sb, sb + STAGE_BYTES, sb + 2 * STAGE_BYTES };

    #pragma unroll
    for (int s = 0; s < 2; s++) {
        #pragma unroll
        for (int i = 0; i < 4; i++) {
            cp16(stb[s] + swo[i], gA[i]);
            cp16(stb[s] + B_OFF + swo[i], gB[i]);
            gA[i] += GBK;
            gB[i] += GBK;
        }
        CP_COMMIT();
    }

    const int a_row0 = wm * 64 + (lane & 15);
    const int b_row0 = wn * 32 + (lane & 15);
    uint32_t a_base[4], b_base[2];
    #pragma unroll
    for (int mf = 0; mf < 4; mf++) {
        const int row = a_row0 + mf * 16;
        a_base[mf] = (uint32_t)row * 128 + (uint32_t)((row & 7) << 4);
    }
    #pragma unroll
    for (int bq = 0; bq < 2; bq++) {
        const int row = b_row0 + bq * 16;
        b_base[bq] = B_OFF + (uint32_t)row * 128 + (uint32_t)((row & 7) << 4);
    }
    const uint32_t khx = (uint32_t)(lane >> 4) << 4;

    int cur = 0, nxt = 2;
    for (int it = 0; it < NIT; it++) {
        if (it + 1 < NIT) cp_wait<1>(); else cp_wait<0>();
        __syncthreads();

        if (it + 2 < NIT) {
            const uint32_t st2 = stb[nxt];
            #pragma unroll
            for (int i = 0; i < 4; i++) {
                cp16(st2 + swo[i], gA[i]);
                cp16(st2 + B_OFF + swo[i], gB[i]);
                gA[i] += GBK;
                gB[i] += GBK;
            }
            CP_COMMIT();
        }

        const uint32_t st = stb[cur];
        #pragma unroll
        for (int ks = 0; ks < 4; ks++) {
            const uint32_t cx = ((uint32_t)(ks * 2) << 4) ^ khx;
            uint32_t Af[4][4], Bf[4][2];
            #pragma unroll
            for (int mf = 0; mf < 4; mf++)
                ldsm_x4(Af[mf], st + (a_base[mf] ^ cx));
            #pragma unroll
            for (int bq = 0; bq < 2; bq++) {
                uint32_t t[4];
                ldsm_x4(t, st + (b_base[bq] ^ cx));
                Bf[bq * 2][0] = t[0];     Bf[bq * 2][1] = t[2];
                Bf[bq * 2 + 1][0] = t[1]; Bf[bq * 2 + 1][1] = t[3];
            }
            #pragma unroll
            for (int mf = 0; mf < 4; mf++)
                #pragma unroll
                for (int nf = 0; nf < 4; nf++)
                    mma16816(acc[mf][nf], Af[mf], Bf[nf]);
        }
        cur = cur == 2 ? 0 : cur + 1;
        nxt = nxt == 2 ? 0 : nxt + 1;
    }

    #pragma unroll
    for (int nf = 0; nf < 4; nf++) {
        const int col = bcol + wn * 32 + nf * 8 + 2 * (lane & 3);
        const float b0 = bias[col], b1 = bias[col + 1];
        #pragma unroll
        for (int mf = 0; mf < 4; mf++) {
            const int r0 = brow + wm * 64 + mf * 16 + (lane >> 2);
            float e0 = acc[mf][nf][0] + b0, e1 = acc[mf][nf][1] + b1;
            float e2 = acc[mf][nf][2] + b0, e3 = acc[mf][nf][3] + b1;
            if (phi) {
                e0 = e0 > 0.0f ? e0 + 1.0f : expf(e0);
                e1 = e1 > 0.0f ? e1 + 1.0f : expf(e1);
                e2 = e2 > 0.0f ? e2 + 1.0f : expf(e2);
                e3 = e3 > 0.0f ? e3 + 1.0f : expf(e3);
            }
            store2(C, (size_t)r0 * FF + col, e0, e1);
            store2(C, (size_t)(r0 + 8) * FF + col, e2, e3);
        }
    }
}

__global__ __launch_bounds__(256, 2)
void mma_qkv(const __half* __restrict__ A, const __half* __restrict__ W,
             const float* __restrict__ b0, const float* __restrict__ b1,
             const float* __restrict__ b2,
             __half* __restrict__ o0, __half* __restrict__ o1, __half* __restrict__ o2)
{
    extern __shared__ char dsm[];
    const int z = blockIdx.z;
    const float* bias = z == 0 ? b0 : (z == 1 ? b1 : b2);
    __half* C = z == 0 ? o0 : (z == 1 ? o1 : o2);
    gemm_core<__half>(A, W + (size_t)z * FF * FF, bias, C, z < 2,
                      blockIdx.y * GBM, blockIdx.x * GBN, dsm);
}

__global__ __launch_bounds__(256, 2)
void mma_o(const __half* __restrict__ A, const __half* __restrict__ W,
           const float* __restrict__ bias, float* __restrict__ C)
{
    extern __shared__ char dsm[];
    gemm_core<float>(A, W, bias, C, false, blockIdx.y * GBM, blockIdx.x * GBN, dsm);
}

// ---------------------------------------------------------------------------
// conv_all: ONE launch. Blocks [0, 2304): weight transpose (4 x 24x24 tiles).
// Blocks [2304, 2304+2048): x -> fp16 (grid-stride over 3.1M float4).
// ---------------------------------------------------------------------------
#define WBLK (4 * (FF / 32) * (FF / 32))   // 2304
#define XBLK 2048
#define XN4  (MROWS * FF / 4)

__global__ __launch_bounds__(256)
void conv_all(const float* __restrict__ W0, const float* __restrict__ W1,
              const float* __restrict__ W2, const float* __restrict__ W3,
              __half* __restrict__ T,
              const float4* __restrict__ xin, __half* __restrict__ x16)
{
    const int blk = blockIdx.x;
    if (blk < WBLK) {
        const int z  = blk / ((FF / 32) * (FF / 32));
        const int r  = blk % ((FF / 32) * (FF / 32));
        const int by = (r / (FF / 32)) * 32;
        const int bx = (r % (FF / 32)) * 32;
        const float* Ws[4] = {W0, W1, W2, W3};
        const float* W = Ws[z];
        __half* th = T + (size_t)z * FF * FF;

        __shared__ float t[32][33];
        const int tx = threadIdx.x & 31, ty = threadIdx.x >> 5;
        #pragma unroll
        for (int i = ty; i < 32; i += 8)
            t[i][tx] = W[(size_t)(by + i) * FF + bx + tx];
        __syncthreads();
        #pragma unroll
        for (int i = ty; i < 32; i += 8)
            th[(size_t)(bx + i) * FF + by + tx] = __float2half_rn(t[tx][i]);
    } else {
        const int xb = blk - WBLK;
        for (int i = xb * 256 + threadIdx.x; i < XN4; i += XBLK * 256) {
            float4 v = xin[i];
            union { __half h[4]; uint2 u; } H;
            H.h[0] = __float2half_rn(v.x);
            H.h[1] = __float2half_rn(v.y);
            H.h[2] = __float2half_rn(v.z);
            H.h[3] = __float2half_rn(v.w);
            *(uint2*)(x16 + 4 * (size_t)i) = H.u;
        }
    }
}

// ---------------------------------------------------------------------------
// kv_partial_mma: per (bh, split) KV^T[e][d] = sum_n v[n][e] k[n][d]
// 256 threads = 2 warp-groups; group g processes chunks {g, g+2}, each with
// its own double buffer (chain length 2). Cross-group fp32 reduce via smem.
// ---------------------------------------------------------------------------
__global__ __launch_bounds__(256)
void kv_partial_mma()
{
    const int bh = blockIdx.x;
    const int sp = blockIdx.y;
    const int b  = bh / NH;
    const int h  = bh % NH;
    const int tid   = threadIdx.x;
    const int warp  = tid >> 5;          // 0..7
    const int lane  = tid & 31;
    const int grp   = warp >> 2;         // 0..1
    const int gwarp = warp & 3;          // 0..3
    const int gtid  = tid & 127;         // tid within group

    // per-group double buffers: [grp][buf]  k,v 4KB each
    __shared__ __align__(16) char kt[2][2][32 * 128];
    __shared__ __align__(16) char vt[2][2][32 * 128];
    __shared__ float red[DH * DH];       // 16KB cross-group reduce
    __shared__ float redks[DH];

    float acc[8][4];
    #pragma unroll
    for (int i = 0; i < 8; i++)
        #pragma unroll
        for (int q = 0; q < 4; q++) acc[i][q] = 0.0f;
    float ksa[8][4];
    #pragma unroll
    for (int i = 0; i < 8; i++)
        #pragma unroll
        for (int q = 0; q < 4; q++) ksa[i][q] = 0.0f;

    const size_t gbase = ((size_t)b * SEQ + (size_t)sp * NPS) * FF + h * DH;
    const int lrow = lane & 15;
    const int lhi  = lane >> 4;

    uint32_t ones[4];
    #pragma unroll
    for (int i = 0; i < 4; i++) ones[i] = 0x3C003C00u;

    // load addressing within group (128 threads fill one 4KB tile: 2 x 16B each)
    const int r0 = gtid >> 3, ch0 = gtid & 7;
    const uint32_t sw0 = (uint32_t)r0 * 128 + (uint32_t)((ch0 ^ (r0 & 7)) << 4);
    const int r1 = r0 + 16;
    const uint32_t sw1 = (uint32_t)r1 * 128 + (uint32_t)((ch0 ^ (r1 & 7)) << 4);

    // group g handles chunks g and g+2 (NCH = 4)
    // prologue: both chunks committed (2 groups in flight per thread)
    #pragma unroll
    for (int s = 0; s < 2; s++) {
        const int c = grp + 2 * s;
        const size_t cb2 = gbase + (size_t)c * 32 * FF;
        const size_t go0 = cb2 + (size_t)r0 * FF + ch0 * 8;
        const size_t go1 = cb2 + (size_t)r1 * FF + ch0 * 8;
        cp16(smem_u32(kt[grp][s]) + sw0, g_k + go0);
        cp16(smem_u32(kt[grp][s]) + sw1, g_k + go1);
        cp16(smem_u32(vt[grp][s]) + sw0, g_v + go0);
        cp16(smem_u32(vt[grp][s]) + sw1, g_v + go1);
        CP_COMMIT();
    }

    #pragma unroll
    for (int s = 0; s < 2; s++) {
        if (s == 0) cp_wait<1>(); else cp_wait<0>();
        __syncthreads();   // group's buffer s fully written (by its own 128 threads)

        const uint32_t kts = smem_u32(kt[grp][s]);
        const uint32_t vts = smem_u32(vt[grp][s]);

        #pragma unroll
        for (int ks2 = 0; ks2 < 2; ks2++) {
            const int nb = ks2 * 16;
            uint32_t t[4], Afr[4];
            {
                const int row = nb + lrow;
                const int ch  = 2 * gwarp + lhi;
                ldsm_x4_t(t, vts + (uint32_t)row * 128
                             + (uint32_t)((ch ^ (row & 7)) << 4));
                Afr[0] = t[0]; Afr[1] = t[2]; Afr[2] = t[1]; Afr[3] = t[3];
            }
            uint32_t Bf[8][2];
            #pragma unroll
            for (int j = 0; j < 4; j++) {
                const int row = nb + lrow;
                const int ch  = 2 * j + lhi;
                uint32_t u[4];
                ldsm_x4_t(u, kts + (uint32_t)row * 128
                             + (uint32_t)((ch ^ (row & 7)) << 4));
                Bf[2 * j][0] = u[0];     Bf[2 * j][1] = u[1];
                Bf[2 * j + 1][0] = u[2]; Bf[2 * j + 1][1] = u[3];
            }
            #pragma unroll
            for (int dg = 0; dg < 8; dg++)
                mma16816(acc[dg], Afr, Bf[dg]);
            if (gwarp == 0) {
                #pragma unroll
                for (int dg = 0; dg < 8; dg++)
                    mma16816(ksa[dg], ones, Bf[dg]);
            }
        }
    }

    // cross-group reduce: group 1 stores, group 0 adds + writes out
    const int g = lane >> 2, tq = lane & 3;
    if (grp == 1) {
        #pragma unroll
        for (int dg = 0; dg < 8; dg++) {
            const int e0 = 16 * gwarp + g;
            const int d0 = 8 * dg + 2 * tq;
            store2(red, (size_t)e0 * DH + d0,       acc[dg][0], acc[dg][1]);
            store2(red, (size_t)(e0 + 8) * DH + d0, acc[dg][2], acc[dg][3]);
        }
        if (gwarp == 0 && g == 0) {
            #pragma unroll
            for (int dg = 0; dg < 8; dg++) {
                redks[8 * dg + 2 * tq]     = ksa[dg][0];
                redks[8 * dg + 2 * tq + 1] = ksa[dg][1];
            }
        }
    }
    __syncthreads();
    if (grp == 0) {
        float* kvout = g_kvp + ((size_t)sp * BH + bh) * DH * DH;
        #pragma unroll
        for (int dg = 0; dg < 8; dg++) {
            const int e0 = 16 * gwarp + g;
            const int d0 = 8 * dg + 2 * tq;
            const size_t i0 = (size_t)e0 * DH + d0;
            const size_t i1 = (size_t)(e0 + 8) * DH + d0;
            store2(kvout, i0, acc[dg][0] + red[i0], acc[dg][1] + red[i0 + 1]);
            store2(kvout, i1, acc[dg][2] + red[i1], acc[dg][3] + red[i1 + 1]);
        }
        if (gwarp == 0 && g == 0) {
            float* ksout = g_ksp + ((size_t)sp * BH + bh) * DH;
            #pragma unroll
            for (int dg = 0; dg < 8; dg++) {
                const int d0 = 8 * dg + 2 * tq;
                ksout[d0]     = ksa[dg][0] + redks[d0];
                ksout[d0 + 1] = ksa[dg][1] + redks[d0 + 1];
            }
        }
    }
}

__global__ __launch_bounds__(256)
void kv_reduce_kernel()
{
    const int idx = blockIdx.x * 256 + threadIdx.x;
    if (idx < BH * DH * DH) {
        float s = 0.0f;
        #pragma unroll
        for (int p = 0; p < NSPLIT; p++) s += g_kvp[(size_t)p * (BH * DH * DH) + idx];
        g_kvT[idx] = __float2half_rn(s);
    }
    if (idx < BH * DH) {
        float s = 0.0f;
        #pragma unroll
        for (int p = 0; p < NSPLIT; p++) s += g_ksp[(size_t)p * (BH * DH) + idx];
        g_ks[idx] = s;
    }
}

// ---------------------------------------------------------------------------
// attn_mma: num = q[128x64] @ KVT^T; out = num * 1/(q.ksum) -> fp16
// ---------------------------------------------------------------------------
__global__ __launch_bounds__(256)
void attn_mma()
{
    const int lt = blockIdx.x;
    const int bh = blockIdx.y;
    const int b  = bh / NH;
    const int h  = bh % NH;
    const int tid  = threadIdx.x;
    const int warp = tid >> 5;
    const int lane = tid & 31;
    const int wm = warp & 3;
    const int we = warp >> 2;

    __shared__ __align__(16) char qs[128 * 128];
    __shared__ __align__(16) char kvs[64 * 128];
    __shared__ float kss[DH];
    __shared__ float zs[128];
    const uint32_t qss = smem_u32(qs);
    const uint32_t kvss = smem_u32(kvs);

    const int lbase = lt * 128;
    const size_t qg = ((size_t)b * SEQ + lbase) * FF + h * DH;

    #pragma unroll
    for (int i = 0; i < 4; i++) {
        const int cid = tid + i * 256;
        const int r = cid >> 3, ch = cid & 7;
        const uint32_t sw = (uint32_t)r * 128 + (uint32_t)((ch ^ (r & 7)) << 4);
        cp16(qss + sw, g_q + qg + (size_t)r * FF + ch * 8);
    }
    #pragma unroll
    for (int i = 0; i < 2; i++) {
        const int cid = tid + i * 256;
        const int r = cid >> 3, ch = cid & 7;
        const uint32_t sw = (uint32_t)r * 128 + (uint32_t)((ch ^ (r & 7)) << 4);
        cp16(kvss + sw, g_kvT + (size_t)bh * DH * DH + (size_t)r * DH + ch * 8);
    }
    if (tid < DH) kss[tid] = g_ks[(size_t)bh * DH + tid];
    CP_COMMIT();
    cp_wait<0>();
    __syncthreads();

    if (tid < 128) {
        const int r = tid;
        float s = 0.0f;
        #pragma unroll
        for (int ch = 0; ch < 8; ch++) {
            uint4 w = *(const uint4*)(qs + (size_t)r * 128 + ((ch ^ (r & 7)) << 4));
            const __half2* h2 = (const __half2*)&w;
            #pragma unroll
            for (int j = 0; j < 4; j++) {
                float2 f = __half22float2(h2[j]);
                s += f.x * kss[ch * 8 + 2 * j] + f.y * kss[ch * 8 + 2 * j + 1];
            }
        }
        zs[r] = 1.0f / s;
    }

    float acc[2][4][4];
    #pragma unroll
    for (int i = 0; i < 2; i++)
        #pragma unroll
        for (int j = 0; j < 4; j++)
            #pragma unroll
            for (int q = 0; q < 4; q++) acc[i][j][q] = 0.0f;

    const int a_row0 = 32 * wm + (lane & 15);
    const int b_row0 = 32 * we + (lane & 15);
    const int lhi = lane >> 4;

    #pragma unroll
    for (int kc = 0; kc < 4; kc++) {
        const int ch = 2 * kc + lhi;
        uint32_t Af[2][4], Bf[4][2];
        #pragma unroll
        for (int mf = 0; mf < 2; mf++) {
            const int row = a_row0 + 16 * mf;
            ldsm_x4(Af[mf], qss + (uint32_t)row * 128
                          + (uint32_t)((ch ^ (row & 7)) << 4));
        }
        #pragma unroll
        for (int bq = 0; bq < 2; bq++) {
            const int row = b_row0 + 16 * bq;
            uint32_t t[4];
            ldsm_x4(t, kvss + (uint32_t)row * 128
                     + (uint32_t)((ch ^ (row & 7)) << 4));
            Bf[bq * 2][0] = t[0];     Bf[bq * 2][1] = t[2];
            Bf[bq * 2 + 1][0] = t[1]; Bf[bq * 2 + 1][1] = t[3];
        }
        #pragma unroll
        for (int mf = 0; mf < 2; mf++)
            #pragma unroll
            for (int nf = 0; nf < 4; nf++)
                mma16816(acc[mf][nf], Af[mf], Bf[nf]);
    }
    __syncthreads();

    const int g = lane >> 2, tq = lane & 3;
    #pragma unroll
    for (int mf = 0; mf < 2; mf++) {
        const int rl0 = 32 * wm + 16 * mf + g;
        const float z0 = zs[rl0], z1 = zs[rl0 + 8];
        const size_t o0 = ((size_t)b * SEQ + lbase + rl0) * FF + h * DH;
        #pragma unroll
        for (int nf = 0; nf < 4; nf++) {
            const int col = 32 * we + 8 * nf + 2 * tq;
            *(__half2*)(g_n + o0 + col) =
                __floats2half2_rn(acc[mf][nf][0] * z0, acc[mf][nf][1] * z0);
            *(__half2*)(g_n + o0 + 8 * (size_t)FF + col) =
                __floats2half2_rn(acc[mf][nf][2] * z1, acc[mf][nf][3] * z1);
        }
    }
}

// ---------------------------------------------------------------------------
// launch
// ---------------------------------------------------------------------------
extern "C" void kernel_launch(void* const* d_in, const int* in_sizes, int n_in,
                              void* d_out, int out_size)
{
    const float* x  = (const float*)d_in[0];
    const float* Wq = (const float*)d_in[1];
    const float* bq = (const float*)d_in[2];
    const float* Wk = (const float*)d_in[3];
    const float* bk = (const float*)d_in[4];
    const float* Wv = (const float*)d_in[5];
    const float* bv = (const float*)d_in[6];
    const float* Wo = (const float*)d_in[7];
    const float* bo = (const float*)d_in[8];
    float* out = (float*)d_out;

    __half *px, *pn, *pw, *pq, *pk, *pv;
    cudaGetSymbolAddress((void**)&px, g_x);
    cudaGetSymbolAddress((void**)&pn, g_n);
    cudaGetSymbolAddress((void**)&pw, g_w);
    cudaGetSymbolAddress((void**)&pq, g_q);
    cudaGetSymbolAddress((void**)&pk, g_k);
    cudaGetSymbolAddress((void**)&pv, g_v);

    cudaFuncSetAttribute((const void*)mma_qkv,
                         cudaFuncAttributeMaxDynamicSharedMemorySize, SMEM_DYN);
    cudaFuncSetAttribute((const void*)mma_o,
                         cudaFuncAttributeMaxDynamicSharedMemorySize, SMEM_DYN);

    // weight transpose + x conversion (single launch)
    conv_all<<<WBLK + XBLK, 256>>>(Wq, Wk, Wv, Wo, pw, (const float4*)x, px);

    // fused q/k/v projections
    mma_qkv<<<dim3(FF / GBN, MROWS / GBM, 3), 256, SMEM_DYN>>>(
        px, pw, bq, bk, bv, pq, pk, pv);

    // kv summary + reduce
    kv_partial_mma<<<dim3(BH, NSPLIT), 256>>>();
    kv_reduce_kernel<<<(BH * DH * DH + 255) / 256, 256>>>();

    // attention output
    attn_mma<<<dim3(SEQ / 128, BH), 256>>>();

    // output projection
    mma_o<<<dim3(FF / GBN, MROWS / GBM), 256, SMEM_DYN>>>(
        pn, pw + 3 * (size_t)FF * FF, bo, out);
}

// round 14
// speedup vs baseline: 1.0202x; 1.0202x over previous
#include <cuda_runtime.h>
#include <cuda_fp16.h>
#include <math.h>
#include <cstdint>

// ---------------------------------------------------------------------------
// Problem dims (fixed by the dataset)
// ---------------------------------------------------------------------------
#define BATCH 4
#define SEQ   4096
#define FF    768
#define NH    12
#define DH    64
#define MROWS (BATCH*SEQ)     // 16384
#define BH    (BATCH*NH)      // 48
#define NSPLIT 16
#define NPS (SEQ / NSPLIT)    // 256 sequence rows per split

// ---------------------------------------------------------------------------
// Static device scratch (no runtime allocation allowed)
// ---------------------------------------------------------------------------
__device__ __half  g_x [MROWS * FF];
__device__ __half  g_q [MROWS * FF];
__device__ __half  g_k [MROWS * FF];
__device__ __half  g_v [MROWS * FF];
__device__ __half  g_n [MROWS * FF];
__device__ __half  g_w [4][FF * FF];              // transposed weights fp16 [n][k]
__device__ float  g_kvp[NSPLIT * BH * DH * DH];
__device__ float  g_ksp[NSPLIT * BH * DH];
__device__ __half g_kvT[BH * DH * DH];
__device__ float  g_ks [BH * DH];

// ---------------------------------------------------------------------------
// PTX helpers
// ---------------------------------------------------------------------------
__device__ __forceinline__ uint32_t smem_u32(const void* p) {
    uint32_t a;
    asm("{ .reg .u64 t; cvta.to.shared.u64 t, %1; cvt.u32.u64 %0, t; }"
        : "=r"(a) : "l"(p));
    return a;
}

__device__ __forceinline__ void cp16(uint32_t dst, const void* src) {
    asm volatile("cp.async.cg.shared.global [%0], [%1], 16;" :: "r"(dst), "l"(src));
}
#define CP_COMMIT() asm volatile("cp.async.commit_group;" ::: "memory")
template <int N>
__device__ __forceinline__ void cp_wait() {
    asm volatile("cp.async.wait_group %0;" :: "n"(N) : "memory");
}

__device__ __forceinline__ void ldsm_x4(uint32_t* r, uint32_t addr) {
    asm volatile("ldmatrix.sync.aligned.m8n8.x4.shared.b16 {%0,%1,%2,%3}, [%4];"
                 : "=r"(r[0]), "=r"(r[1]), "=r"(r[2]), "=r"(r[3]) : "r"(addr));
}
__device__ __forceinline__ void ldsm_x4_t(uint32_t* r, uint32_t addr) {
    asm volatile("ldmatrix.sync.aligned.m8n8.x4.trans.shared.b16 {%0,%1,%2,%3}, [%4];"
                 : "=r"(r[0]), "=r"(r[1]), "=r"(r[2]), "=r"(r[3]) : "r"(addr));
}

__device__ __forceinline__ void mma16816(float* d, const uint32_t* a, const uint32_t* b) {
    asm volatile(
        "mma.sync.aligned.m16n8k16.row.col.f32.f16.f16.f32 "
        "{%0,%1,%2,%3}, {%4,%5,%6,%7}, {%8,%9}, {%0,%1,%2,%3};"
        : "+f"(d[0]), "+f"(d[1]), "+f"(d[2]), "+f"(d[3])
        : "r"(a[0]), "r"(a[1]), "r"(a[2]), "r"(a[3]), "r"(b[0]), "r"(b[1]));
}

__device__ __forceinline__ void store2(float* C, size_t idx, float a, float b) {
    *(float2*)(C + idx) = make_float2(a, b);
}
__device__ __forceinline__ void store2(__half* C, size_t idx, float a, float b) {
    *(__half2*)(C + idx) = __floats2half2_rn(a, b);
}

// ---------------------------------------------------------------------------
// gemm core: C tile = A[M,K] @ W[N,K]^T + bias, optional phi
// CTA 128x128, BK=64, 256 threads = 8 warps (2Mx4N), warp 64x32.
// 3-stage cp.async ring (96KB), prefetch distance 2, ONE barrier/iter.
// ---------------------------------------------------------------------------
#define GBM 128
#define GBN 128
#define GBK 64
#define A_BYTES  (128 * 128)
#define B_OFF  A_BYTES
#define STAGE_BYTES (2 * A_BYTES)      // 32 KB
#define SMEM_DYN (3 * STAGE_BYTES)     // 96 KB
#define NIT (FF / GBK)                 // 12

template <typename OutT>
__device__ __forceinline__ void gemm_core(
        const __half* __restrict__ A, const __half* __restrict__ B,
        const float* __restrict__ bias, OutT* __restrict__ C,
        bool phi, int brow, int bcol, char* dsm)
{
    const uint32_t sb = smem_u32(dsm);
    const int tid  = threadIdx.x;
    const int warp = tid >> 5;
    const int lane = tid & 31;
    const int wm   = warp & 1;
    const int wn   = warp >> 1;

    float acc[4][4][4];
    #pragma unroll
    for (int i = 0; i < 4; i++)
        #pragma unroll
        for (int j = 0; j < 4; j++)
            #pragma unroll
            for (int q = 0; q < 4; q++) acc[i][j][q] = 0.0f;

    const int lr = tid >> 3, lc = tid & 7;
    uint32_t swo[4];
    const __half* gA[4];
    const __half* gB[4];
    #pragma unroll
    for (int i = 0; i < 4; i++) {
        const int row = lr + 32 * i;
        swo[i] = (uint32_t)row * 128 + (uint32_t)((lc ^ (row & 7)) << 4);
        gA[i] = A + (size_t)(brow + row) * FF + lc * 8;
        gB[i] = B + (size_t)(bcol + row) * FF + lc * 8;
    }

    const uint32_t stb[3] = { sb, sb + STAGE_BYTES, sb + 2 * STAGE_BYTES };

    #pragma unroll
    for (int s = 0; s < 2; s++) {
        #pragma unroll
        for (int i = 0; i < 4; i++) {
            cp16(stb[s] + swo[i], gA[i]);
            cp16(stb[s] + B_OFF + swo[i], gB[i]);
            gA[i] += GBK;
            gB[i] += GBK;
        }
        CP_COMMIT();
    }

    const int a_row0 = wm * 64 + (lane & 15);
    const int b_row0 = wn * 32 + (lane & 15);
    uint32_t a_base[4], b_base[2];
    #pragma unroll
    for (int mf = 0; mf < 4; mf++) {
        const int row = a_row0 + mf * 16;
        a_base[mf] = (uint32_t)row * 128 + (uint32_t)((row & 7) << 4);
    }
    #pragma unroll
    for (int bq = 0; bq < 2; bq++) {
        const int row = b_row0 + bq * 16;
        b_base[bq] = B_OFF + (uint32_t)row * 128 + (uint32_t)((row & 7) << 4);
    }
    const uint32_t khx = (uint32_t)(lane >> 4) << 4;

    int cur = 0, nxt = 2;
    for (int it = 0; it < NIT; it++) {
        if (it + 1 < NIT) cp_wait<1>(); else cp_wait<0>();
        __syncthreads();

        if (it + 2 < NIT) {
            const uint32_t st2 = stb[nxt];
            #pragma unroll
            for (int i = 0; i < 4; i++) {
                cp16(st2 + swo[i], gA[i]);
                cp16(st2 + B_OFF + swo[i], gB[i]);
                gA[i] += GBK;
                gB[i] += GBK;
            }
            CP_COMMIT();
        }

        const uint32_t st = stb[cur];
        #pragma unroll
        for (int ks = 0; ks < 4; ks++) {
            const uint32_t cx = ((uint32_t)(ks * 2) << 4) ^ khx;
            uint32_t Af[4][4], Bf[4][2];
            #pragma unroll
            for (int mf = 0; mf < 4; mf++)
                ldsm_x4(Af[mf], st + (a_base[mf] ^ cx));
            #pragma unroll
            for (int bq = 0; bq < 2; bq++) {
                uint32_t t[4];
                ldsm_x4(t, st + (b_base[bq] ^ cx));
                Bf[bq * 2][0] = t[0];     Bf[bq * 2][1] = t[2];
                Bf[bq * 2 + 1][0] = t[1]; Bf[bq * 2 + 1][1] = t[3];
            }
            #pragma unroll
            for (int mf = 0; mf < 4; mf++)
                #pragma unroll
                for (int nf = 0; nf < 4; nf++)
                    mma16816(acc[mf][nf], Af[mf], Bf[nf]);
        }
        cur = cur == 2 ? 0 : cur + 1;
        nxt = nxt == 2 ? 0 : nxt + 1;
    }

    #pragma unroll
    for (int nf = 0; nf < 4; nf++) {
        const int col = bcol + wn * 32 + nf * 8 + 2 * (lane & 3);
        const float b0 = bias[col], b1 = bias[col + 1];
        #pragma unroll
        for (int mf = 0; mf < 4; mf++) {
            const int r0 = brow + wm * 64 + mf * 16 + (lane >> 2);
            float e0 = acc[mf][nf][0] + b0, e1 = acc[mf][nf][1] + b1;
            float e2 = acc[mf][nf][2] + b0, e3 = acc[mf][nf][3] + b1;
            if (phi) {
                e0 = e0 > 0.0f ? e0 + 1.0f : expf(e0);
                e1 = e1 > 0.0f ? e1 + 1.0f : expf(e1);
                e2 = e2 > 0.0f ? e2 + 1.0f : expf(e2);
                e3 = e3 > 0.0f ? e3 + 1.0f : expf(e3);
            }
            store2(C, (size_t)r0 * FF + col, e0, e1);
            store2(C, (size_t)(r0 + 8) * FF + col, e2, e3);
        }
    }
}

__global__ __launch_bounds__(256, 2)
void mma_qkv(const __half* __restrict__ A, const __half* __restrict__ W,
             const float* __restrict__ b0, const float* __restrict__ b1,
             const float* __restrict__ b2,
             __half* __restrict__ o0, __half* __restrict__ o1, __half* __restrict__ o2)
{
    extern __shared__ char dsm[];
    const int z = blockIdx.z;
    const float* bias = z == 0 ? b0 : (z == 1 ? b1 : b2);
    __half* C = z == 0 ? o0 : (z == 1 ? o1 : o2);
    gemm_core<__half>(A, W + (size_t)z * FF * FF, bias, C, z < 2,
                      blockIdx.y * GBM, blockIdx.x * GBN, dsm);
}

__global__ __launch_bounds__(256, 2)
void mma_o(const __half* __restrict__ A, const __half* __restrict__ W,
           const float* __restrict__ bias, float* __restrict__ C)
{
    extern __shared__ char dsm[];
    gemm_core<float>(A, W, bias, C, false, blockIdx.y * GBM, blockIdx.x * GBN, dsm);
}

// ---------------------------------------------------------------------------
// conv_all: ONE launch. Blocks [0, 2304): weight transpose.
// Blocks [2304, 2304+2048): x -> fp16.
// ---------------------------------------------------------------------------
#define WBLK (4 * (FF / 32) * (FF / 32))   // 2304
#define XBLK 2048
#define XN4  (MROWS * FF / 4)

__global__ __launch_bounds__(256)
void conv_all(const float* __restrict__ W0, const float* __restrict__ W1,
              const float* __restrict__ W2, const float* __restrict__ W3,
              __half* __restrict__ T,
              const float4* __restrict__ xin, __half* __restrict__ x16)
{
    const int blk = blockIdx.x;
    if (blk < WBLK) {
        const int z  = blk / ((FF / 32) * (FF / 32));
        const int r  = blk % ((FF / 32) * (FF / 32));
        const int by = (r / (FF / 32)) * 32;
        const int bx = (r % (FF / 32)) * 32;
        const float* Ws[4] = {W0, W1, W2, W3};
        const float* W = Ws[z];
        __half* th = T + (size_t)z * FF * FF;

        __shared__ float t[32][33];
        const int tx = threadIdx.x & 31, ty = threadIdx.x >> 5;
        #pragma unroll
        for (int i = ty; i < 32; i += 8)
            t[i][tx] = W[(size_t)(by + i) * FF + bx + tx];
        __syncthreads();
        #pragma unroll
        for (int i = ty; i < 32; i += 8)
            th[(size_t)(bx + i) * FF + by + tx] = __float2half_rn(t[tx][i]);
    } else {
        const int xb = blk - WBLK;
        for (int i = xb * 256 + threadIdx.x; i < XN4; i += XBLK * 256) {
            float4 v = xin[i];
            union { __half h[4]; uint2 u; } H;
            H.h[0] = __float2half_rn(v.x);
            H.h[1] = __float2half_rn(v.y);
            H.h[2] = __float2half_rn(v.z);
            H.h[3] = __float2half_rn(v.w);
            *(uint2*)(x16 + 4 * (size_t)i) = H.u;
        }
    }
}

// ---------------------------------------------------------------------------
// kv_partial_mma: per (bh, split) KV^T[e][d] = sum_n v[n][e] k[n][d]
// 3-stage cp.async ring, ONE barrier per 32-row chunk. (R12-validated form)
// ---------------------------------------------------------------------------
__global__ __launch_bounds__(128)
void kv_partial_mma()
{
    const int bh = blockIdx.x;
    const int sp = blockIdx.y;
    const int b  = bh / NH;
    const int h  = bh % NH;
    const int tid  = threadIdx.x;
    const int warp = tid >> 5;
    const int lane = tid & 31;

    __shared__ __align__(16) char kt[3][32 * 128];
    __shared__ __align__(16) char vt[3][32 * 128];

    float acc[8][4];
    #pragma unroll
    for (int i = 0; i < 8; i++)
        #pragma unroll
        for (int q = 0; q < 4; q++) acc[i][q] = 0.0f;
    float ksa[8][4];
    #pragma unroll
    for (int i = 0; i < 8; i++)
        #pragma unroll
        for (int q = 0; q < 4; q++) ksa[i][q] = 0.0f;

    const size_t gbase = ((size_t)b * SEQ + (size_t)sp * NPS) * FF + h * DH;
    const int lrow = lane & 15;
    const int lhi  = lane >> 4;

    uint32_t ones[4];
    #pragma unroll
    for (int i = 0; i < 4; i++) ones[i] = 0x3C003C00u;

    const int r0 = tid >> 3, ch0 = tid & 7;
    const uint32_t sw0 = (uint32_t)r0 * 128 + (uint32_t)((ch0 ^ (r0 & 7)) << 4);
    const int r1 = r0 + 16;
    const uint32_t sw1 = (uint32_t)r1 * 128 + (uint32_t)((ch0 ^ (r1 & 7)) << 4);

    const int NCH = NPS / 32;   // 8

    #pragma unroll
    for (int s = 0; s < 2; s++) {
        const size_t cb2 = gbase + (size_t)s * 32 * FF;
        const size_t go0 = cb2 + (size_t)r0 * FF + ch0 * 8;
        const size_t go1 = cb2 + (size_t)r1 * FF + ch0 * 8;
        cp16(smem_u32(kt[s]) + sw0, g_k + go0);
        cp16(smem_u32(kt[s]) + sw1, g_k + go1);
        cp16(smem_u32(vt[s]) + sw0, g_v + go0);
        cp16(smem_u32(vt[s]) + sw1, g_v + go1);
        CP_COMMIT();
    }

    int cur = 0, nxt = 2;
    for (int c = 0; c < NCH; c++) {
        if (c + 1 < NCH) cp_wait<1>(); else cp_wait<0>();
        __syncthreads();

        if (c + 2 < NCH) {
            const size_t cb2 = gbase + (size_t)(c + 2) * 32 * FF;
            const size_t go0 = cb2 + (size_t)r0 * FF + ch0 * 8;
            const size_t go1 = cb2 + (size_t)r1 * FF + ch0 * 8;
            cp16(smem_u32(kt[nxt]) + sw0, g_k + go0);
            cp16(smem_u32(kt[nxt]) + sw1, g_k + go1);
            cp16(smem_u32(vt[nxt]) + sw0, g_v + go0);
            cp16(smem_u32(vt[nxt]) + sw1, g_v + go1);
            CP_COMMIT();
        }

        const uint32_t kts = smem_u32(kt[cur]);
        const uint32_t vts = smem_u32(vt[cur]);

        #pragma unroll
        for (int ks2 = 0; ks2 < 2; ks2++) {
            const int nb = ks2 * 16;
            uint32_t t[4], Afr[4];
            {
                const int row = nb + lrow;
                const int ch  = 2 * warp + lhi;
                ldsm_x4_t(t, vts + (uint32_t)row * 128
                             + (uint32_t)((ch ^ (row & 7)) << 4));
                Afr[0] = t[0]; Afr[1] = t[2]; Afr[2] = t[1]; Afr[3] = t[3];
            }
            uint32_t Bf[8][2];
            #pragma unroll
            for (int j = 0; j < 4; j++) {
                const int row = nb + lrow;
                const int ch  = 2 * j + lhi;
                uint32_t u[4];
                ldsm_x4_t(u, kts + (uint32_t)row * 128
                             + (uint32_t)((ch ^ (row & 7)) << 4));
                Bf[2 * j][0] = u[0];     Bf[2 * j][1] = u[1];
                Bf[2 * j + 1][0] = u[2]; Bf[2 * j + 1][1] = u[3];
            }
            #pragma unroll
            for (int dg = 0; dg < 8; dg++)
                mma16816(acc[dg], Afr, Bf[dg]);
            if (warp == 0) {
                #pragma unroll
                for (int dg = 0; dg < 8; dg++)
                    mma16816(ksa[dg], ones, Bf[dg]);
            }
        }
        cur = cur == 2 ? 0 : cur + 1;
        nxt = nxt == 2 ? 0 : nxt + 1;
    }

    const int g = lane >> 2, tq = lane & 3;
    float* kvout = g_kvp + ((size_t)sp * BH + bh) * DH * DH;
    #pragma unroll
    for (int dg = 0; dg < 8; dg++) {
        const int e0 = 16 * warp + g;
        const int d0 = 8 * dg + 2 * tq;
        store2(kvout, (size_t)e0 * DH + d0,       acc[dg][0], acc[dg][1]);
        store2(kvout, (size_t)(e0 + 8) * DH + d0, acc[dg][2], acc[dg][3]);
    }
    if (warp == 0 && g == 0) {
        float* ksout = g_ksp + ((size_t)sp * BH + bh) * DH;
        #pragma unroll
        for (int dg = 0; dg < 8; dg++) {
            ksout[8 * dg + 2 * tq]     = ksa[dg][0];
            ksout[8 * dg + 2 * tq + 1] = ksa[dg][1];
        }
    }
}

__global__ __launch_bounds__(256)
void kv_reduce_kernel()
{
    const int idx = blockIdx.x * 256 + threadIdx.x;
    if (idx < BH * DH * DH) {
        float s = 0.0f;
        #pragma unroll
        for (int p = 0; p < NSPLIT; p++) s += g_kvp[(size_t)p * (BH * DH * DH) + idx];
        g_kvT[idx] = __float2half_rn(s);
    }
    if (idx < BH * DH) {
        float s = 0.0f;
        #pragma unroll
        for (int p = 0; p < NSPLIT; p++) s += g_ksp[(size_t)p * (BH * DH) + idx];
        g_ks[idx] = s;
    }
}

// ---------------------------------------------------------------------------
// attn_mma: per CTA: TWO 128-row q tiles (double-buffered), kvT loaded once.
// num = q @ KVT^T; out = num * 1/(q.ksum) -> fp16.
// grid (SEQ/256, BH), 256 threads = 8 warps (4 l x 2 e), warp 32x32.
// ---------------------------------------------------------------------------
__global__ __launch_bounds__(256)
void attn_mma()
{
    const int lt2 = blockIdx.x;           // 256-row super-tile
    const int bh  = blockIdx.y;
    const int b   = bh / NH;
    const int h   = bh % NH;
    const int tid  = threadIdx.x;
    const int warp = tid >> 5;
    const int lane = tid & 31;
    const int wm = warp & 3;
    const int we = warp >> 2;

    __shared__ __align__(16) char qs[2][128 * 128];   // two q tiles
    __shared__ __align__(16) char kvs[64 * 128];
    __shared__ float kss[DH];
    __shared__ float zs[2][128];
    const uint32_t kvss = smem_u32(kvs);

    const size_t qg = ((size_t)b * SEQ + (size_t)lt2 * 256) * FF + h * DH;

    // group 0: kvT + kss + q tile 0 ; group 1: q tile 1
    {
        #pragma unroll
        for (int i = 0; i < 2; i++) {
            const int cid = tid + i * 256;
            const int r = cid >> 3, ch = cid & 7;
            const uint32_t sw = (uint32_t)r * 128 + (uint32_t)((ch ^ (r & 7)) << 4);
            cp16(kvss + sw, g_kvT + (size_t)bh * DH * DH + (size_t)r * DH + ch * 8);
        }
        #pragma unroll
        for (int i = 0; i < 4; i++) {
            const int cid = tid + i * 256;
            const int r = cid >> 3, ch = cid & 7;
            const uint32_t sw = (uint32_t)r * 128 + (uint32_t)((ch ^ (r & 7)) << 4);
            cp16(smem_u32(qs[0]) + sw, g_q + qg + (size_t)r * FF + ch * 8);
        }
        CP_COMMIT();
        #pragma unroll
        for (int i = 0; i < 4; i++) {
            const int cid = tid + i * 256;
            const int r = cid >> 3, ch = cid & 7;
            const uint32_t sw = (uint32_t)r * 128 + (uint32_t)((ch ^ (r & 7)) << 4);
            cp16(smem_u32(qs[1]) + sw, g_q + qg + (size_t)(r + 128) * FF + ch * 8);
        }
        CP_COMMIT();
        if (tid < DH) kss[tid] = g_ks[(size_t)bh * DH + tid];
    }

    const int a_row0 = 32 * wm + (lane & 15);
    const int b_row0 = 32 * we + (lane & 15);
    const int lhi = lane >> 4;
    const int g = lane >> 2, tq = lane & 3;

    #pragma unroll
    for (int half = 0; half < 2; half++) {
        if (half == 0) cp_wait<1>(); else cp_wait<0>();
        __syncthreads();

        const uint32_t qss = smem_u32(qs[half]);

        // z = 1/(q.ksum) for this tile's 128 rows (threads 0-127)
        if (tid < 128) {
            const int r = tid;
            float s = 0.0f;
            #pragma unroll
            for (int ch = 0; ch < 8; ch++) {
                uint4 w = *(const uint4*)(qs[half] + (size_t)r * 128
                                          + ((ch ^ (r & 7)) << 4));
                const __half2* h2 = (const __half2*)&w;
                #pragma unroll
                for (int j = 0; j < 4; j++) {
                    float2 f = __half22float2(h2[j]);
                    s += f.x * kss[ch * 8 + 2 * j] + f.y * kss[ch * 8 + 2 * j + 1];
                }
            }
            zs[half][r] = 1.0f / s;
        }

        float acc[2][4][4];
        #pragma unroll
        for (int i = 0; i < 2; i++)
            #pragma unroll
            for (int j = 0; j < 4; j++)
                #pragma unroll
                for (int q = 0; q < 4; q++) acc[i][j][q] = 0.0f;

        #pragma unroll
        for (int kc = 0; kc < 4; kc++) {
            const int ch = 2 * kc + lhi;
            uint32_t Af[2][4], Bf[4][2];
            #pragma unroll
            for (int mf = 0; mf < 2; mf++) {
                const int row = a_row0 + 16 * mf;
                ldsm_x4(Af[mf], qss + (uint32_t)row * 128
                              + (uint32_t)((ch ^ (row & 7)) << 4));
            }
            #pragma unroll
            for (int bq = 0; bq < 2; bq++) {
                const int row = b_row0 + 16 * bq;
                uint32_t t[4];
                ldsm_x4(t, kvss + (uint32_t)row * 128
                         + (uint32_t)((ch ^ (row & 7)) << 4));
                Bf[bq * 2][0] = t[0];     Bf[bq * 2][1] = t[2];
                Bf[bq * 2 + 1][0] = t[1]; Bf[bq * 2 + 1][1] = t[3];
            }
            #pragma unroll
            for (int mf = 0; mf < 2; mf++)
                #pragma unroll
                for (int nf = 0; nf < 4; nf++)
                    mma16816(acc[mf][nf], Af[mf], Bf[nf]);
        }
        __syncthreads();   // zs[half] ready

        #pragma unroll
        for (int mf = 0; mf < 2; mf++) {
            const int rl0 = 32 * wm + 16 * mf + g;
            const float z0 = zs[half][rl0], z1 = zs[half][rl0 + 8];
            const size_t o0 = ((size_t)b * SEQ + (size_t)lt2 * 256 + half * 128 + rl0)
                              * FF + h * DH;
            #pragma unroll
            for (int nf = 0; nf < 4; nf++) {
                const int col = 32 * we + 8 * nf + 2 * tq;
                *(__half2*)(g_n + o0 + col) =
                    __floats2half2_rn(acc[mf][nf][0] * z0, acc[mf][nf][1] * z0);
                *(__half2*)(g_n + o0 + 8 * (size_t)FF + col) =
                    __floats2half2_rn(acc[mf][nf][2] * z1, acc[mf][nf][3] * z1);
            }
        }
    }
}

// ---------------------------------------------------------------------------
// launch
// ---------------------------------------------------------------------------
extern "C" void kernel_launch(void* const* d_in, const int* in_sizes, int n_in,
                              void* d_out, int out_size)
{
    const float* x  = (const float*)d_in[0];
    const float* Wq = (const float*)d_in[1];
    const float* bq = (const float*)d_in[2];
    const float* Wk = (const float*)d_in[3];
    const float* bk = (const float*)d_in[4];
    const float* Wv = (const float*)d_in[5];
    const float* bv = (const float*)d_in[6];
    const float* Wo = (const float*)d_in[7];
    const float* bo = (const float*)d_in[8];
    float* out = (float*)d_out;

    __half *px, *pn, *pw, *pq, *pk, *pv;
    cudaGetSymbolAddress((void**)&px, g_x);
    cudaGetSymbolAddress((void**)&pn, g_n);
    cudaGetSymbolAddress((void**)&pw, g_w);
    cudaGetSymbolAddress((void**)&pq, g_q);
    cudaGetSymbolAddress((void**)&pk, g_k);
    cudaGetSymbolAddress((void**)&pv, g_v);

    cudaFuncSetAttribute((const void*)mma_qkv,
                         cudaFuncAttributeMaxDynamicSharedMemorySize, SMEM_DYN);
    cudaFuncSetAttribute((const void*)mma_o,
                         cudaFuncAttributeMaxDynamicSharedMemorySize, SMEM_DYN);

    // weight transpose + x conversion (single launch)
    conv_all<<<WBLK + XBLK, 256>>>(Wq, Wk, Wv, Wo, pw, (const float4*)x, px);

    // fused q/k/v projections
    mma_qkv<<<dim3(FF / GBN, MROWS / GBM, 3), 256, SMEM_DYN>>>(
        px, pw, bq, bk, bv, pq, pk, pv);

    // kv summary + reduce
    kv_partial_mma<<<dim3(BH, NSPLIT), 128>>>();
    kv_reduce_kernel<<<(BH * DH * DH + 255) / 256, 256>>>();

    // attention output (two q tiles per CTA, double-buffered)
    attn_mma<<<dim3(SEQ / 256, BH), 256>>>();

    // output projection
    mma_o<<<dim3(FF / GBN, MROWS / GBM), 256, SMEM_DYN>>>(
        pn, pw + 3 * (size_t)FF * FF, bo, out);
}